// round 5
// baseline (speedup 1.0000x reference)
#include <cuda_runtime.h>
#include <math.h>

// ---------------------------------------------------------------------------
// Problem constants
// ---------------------------------------------------------------------------
#define BATCH 8
#define LSEQ 341          // 5 + 16 + 64 + 256
#define PATCH_LEN 340
#define PDIM 192
#define DMODEL 1024
#define NHEAD 16
#define HDIM 64
#define NDEPTH 8
#define MLPDIM 4096
#define ROWS (BATCH * LSEQ)        // 2728
#define PROWS (BATCH * PATCH_LEN)  // 2720

// ---------------------------------------------------------------------------
// Scratch (device globals: no allocation allowed)
// ---------------------------------------------------------------------------
__device__ float g_x[ROWS * DMODEL];
__device__ float g_h[ROWS * DMODEL];
__device__ float g_qkv[ROWS * 3 * DMODEL];
__device__ float g_o[ROWS * DMODEL];
__device__ float g_mlp[ROWS * MLPDIM];
__device__ float g_ada[BATCH * 6 * DMODEL];
__device__ float g_cond[BATCH * DMODEL];
__device__ float g_silu[BATCH * DMODEL];
__device__ float g_hada[BATCH * 2 * DMODEL];

__device__ __forceinline__ int stage_of(int l) {
    return (l < 5) ? 0 : (l < 21) ? 1 : (l < 85) ? 2 : 3;
}
__device__ __forceinline__ int end_of(int l) {
    return (l < 5) ? 5 : (l < 21) ? 21 : (l < 85) ? 85 : 341;
}

__device__ __forceinline__ float gelu_tanh(float x) {
    // jax.nn.gelu default (approximate=True)
    float x3 = x * x * x;
    return 0.5f * x * (1.f + tanhf(0.7978845608028654f * (x + 0.044715f * x3)));
}

// ---------------------------------------------------------------------------
// cond gather + silu
// ---------------------------------------------------------------------------
__global__ void k_cond(const float* __restrict__ class_emb,
                       const int* __restrict__ labels) {
    int b = blockIdx.y;
    int d = blockIdx.x * 256 + threadIdx.x;
    float c = class_emb[labels[b] * DMODEL + d];
    g_cond[b * DMODEL + d] = c;
    g_silu[b * DMODEL + d] = c / (1.f + expf(-c));
}

// ---------------------------------------------------------------------------
// Assemble x = concat(cond, tok) + pos + scale_emb[SID] (+ b_patch on tok)
// ---------------------------------------------------------------------------
__global__ void k_assemble(const float* __restrict__ pos,
                           const float* __restrict__ scale_emb,
                           const float* __restrict__ b_patch) {
    int idx = blockIdx.x * 256 + threadIdx.x;
    if (idx >= ROWS * DMODEL) return;
    int d = idx & (DMODEL - 1);
    int r = idx >> 10;
    int b = r / LSEQ;
    int l = r - b * LSEQ;
    float v;
    if (l == 0) v = g_cond[b * DMODEL + d];
    else        v = g_h[(b * PATCH_LEN + l - 1) * DMODEL + d] + b_patch[d];
    v += pos[l * DMODEL + d] + scale_emb[stage_of(l) * DMODEL + d];
    g_x[idx] = v;
}

// ---------------------------------------------------------------------------
// Tiled SGEMM, double-buffered, conflict-free 2x2 fragment layout.
// C[M,N] = A[M,K] @ B[K,N] (+ bias) + epilogue.
// Each thread computes a 2x2 grid of 4x4 sub-tiles:
//   rows {ty*4..+3} and {64+ty*4..+3}; cols {tx*4..+3} and {64+tx*4..+3}.
// All smem operand reads are aligned LDS.128, conflict-free.
// epi: 0=none, 1=gelu, 2=gated residual (C += gate * (acc+bias)), gate from
//      g_ada[b*6144 + gateOff + col], b = row / LSEQ.
// ---------------------------------------------------------------------------
#define EPI_NONE 0
#define EPI_GELU 1
#define EPI_GATE 2

__global__ __launch_bounds__(256)
void k_sgemm(const float* __restrict__ A, const float* __restrict__ Bm,
             const float* __restrict__ bias, float* __restrict__ C,
             int M, int N, int K, int epi, int gateOff) {
    __shared__ float As[2][16][128];
    __shared__ float Bs[2][16][128];

    int tid = threadIdx.x;
    int brow = blockIdx.y * 128;
    int bcol = blockIdx.x * 128;

    int ar  = tid >> 2;           // 0..63   (A row within tile, +64 for s=1)
    int ac4 = (tid & 3) * 4;      // 0,4,8,12 (A k-offset, float4)
    int br  = tid >> 5;           // 0..7    (B k-row within tile, +8 for s=1)
    int bc4 = (tid & 31) * 4;     // 0..124  (B col, float4)
    int tx  = tid & 15;
    int ty  = tid >> 4;

    // acc[ih][jh][i][j]: row = brow + ih*64 + ty*4 + i, col = bcol + jh*64 + tx*4 + j
    float acc[2][2][4][4];
#pragma unroll
    for (int ih = 0; ih < 2; ih++)
#pragma unroll
        for (int jh = 0; jh < 2; jh++)
#pragma unroll
            for (int i = 0; i < 4; i++)
#pragma unroll
                for (int j = 0; j < 4; j++) acc[ih][jh][i][j] = 0.f;

    const int nk = K >> 4;
    float4 aReg[2], bReg[2];

    // ---- prologue: load tile 0 into buffer 0 ----
#pragma unroll
    for (int s = 0; s < 2; s++) {
        int row = brow + ar + s * 64;
        aReg[s] = make_float4(0.f, 0.f, 0.f, 0.f);
        if (row < M) aReg[s] = *(const float4*)(A + row * K + ac4);
        int kr = br + s * 8;
        int col = bcol + bc4;
        bReg[s] = make_float4(0.f, 0.f, 0.f, 0.f);
        if (col < N) bReg[s] = *(const float4*)(Bm + kr * N + col);
    }
#pragma unroll
    for (int s = 0; s < 2; s++) {
        As[0][ac4 + 0][ar + s * 64] = aReg[s].x;
        As[0][ac4 + 1][ar + s * 64] = aReg[s].y;
        As[0][ac4 + 2][ar + s * 64] = aReg[s].z;
        As[0][ac4 + 3][ar + s * 64] = aReg[s].w;
        *(float4*)&Bs[0][br + s * 8][bc4] = bReg[s];
    }
    __syncthreads();

    for (int kt = 0; kt < nk; kt++) {
        int p = kt & 1;

        // ---- issue global loads for next tile (overlap with compute) ----
        if (kt + 1 < nk) {
            int k0n = (kt + 1) << 4;
#pragma unroll
            for (int s = 0; s < 2; s++) {
                int row = brow + ar + s * 64;
                aReg[s] = make_float4(0.f, 0.f, 0.f, 0.f);
                if (row < M) aReg[s] = *(const float4*)(A + row * K + k0n + ac4);
                int kr = k0n + br + s * 8;
                int col = bcol + bc4;
                bReg[s] = make_float4(0.f, 0.f, 0.f, 0.f);
                if (col < N) bReg[s] = *(const float4*)(Bm + kr * N + col);
            }
        }

        // ---- compute on buffer p ----
#pragma unroll
        for (int k = 0; k < 16; k++) {
            float4 a0 = *(const float4*)&As[p][k][ty * 4];
            float4 a1 = *(const float4*)&As[p][k][64 + ty * 4];
            float4 b0 = *(const float4*)&Bs[p][k][tx * 4];
            float4 b1 = *(const float4*)&Bs[p][k][64 + tx * 4];
            float av[2][4] = {{a0.x, a0.y, a0.z, a0.w}, {a1.x, a1.y, a1.z, a1.w}};
            float bv[2][4] = {{b0.x, b0.y, b0.z, b0.w}, {b1.x, b1.y, b1.z, b1.w}};
#pragma unroll
            for (int ih = 0; ih < 2; ih++)
#pragma unroll
                for (int jh = 0; jh < 2; jh++)
#pragma unroll
                    for (int i = 0; i < 4; i++)
#pragma unroll
                        for (int j = 0; j < 4; j++)
                            acc[ih][jh][i][j] += av[ih][i] * bv[jh][j];
        }

        // ---- stage next tile into the other buffer ----
        if (kt + 1 < nk) {
            int q = p ^ 1;
#pragma unroll
            for (int s = 0; s < 2; s++) {
                As[q][ac4 + 0][ar + s * 64] = aReg[s].x;
                As[q][ac4 + 1][ar + s * 64] = aReg[s].y;
                As[q][ac4 + 2][ar + s * 64] = aReg[s].z;
                As[q][ac4 + 3][ar + s * 64] = aReg[s].w;
                *(float4*)&Bs[q][br + s * 8][bc4] = bReg[s];
            }
            __syncthreads();
        }
    }

    // ---- epilogue ----
    float bcache[2][4];
#pragma unroll
    for (int jh = 0; jh < 2; jh++)
#pragma unroll
        for (int j = 0; j < 4; j++) {
            int col = bcol + jh * 64 + tx * 4 + j;
            bcache[jh][j] = (bias && col < N) ? bias[col] : 0.f;
        }

#pragma unroll
    for (int ih = 0; ih < 2; ih++)
#pragma unroll
        for (int i = 0; i < 4; i++) {
            int row = brow + ih * 64 + ty * 4 + i;
            if (row >= M) continue;
            int bidx = row / LSEQ;
#pragma unroll
            for (int jh = 0; jh < 2; jh++)
#pragma unroll
                for (int j = 0; j < 4; j++) {
                    int col = bcol + jh * 64 + tx * 4 + j;
                    if (col >= N) continue;
                    float v = acc[ih][jh][i][j] + bcache[jh][j];
                    int off = row * N + col;
                    if (epi == EPI_GELU) {
                        C[off] = gelu_tanh(v);
                    } else if (epi == EPI_GATE) {
                        float g = g_ada[bidx * 6144 + gateOff + col];
                        C[off] = C[off] + g * v;
                    } else {
                        C[off] = v;
                    }
                }
        }
}

// ---------------------------------------------------------------------------
// ada = silu(cond) @ W + b  (M = 8, tiny)
// ---------------------------------------------------------------------------
__global__ void k_ada(const float* __restrict__ W, const float* __restrict__ bias,
                      float* __restrict__ out, int N) {
    int t = blockIdx.x * 256 + threadIdx.x;
    if (t >= BATCH * N) return;
    int b = t / N;
    int n = t - b * N;
    const float* s = g_silu + b * DMODEL;
    float acc = 0.f;
#pragma unroll 4
    for (int k = 0; k < DMODEL; k++) acc += s[k] * W[k * N + n];
    out[t] = acc + bias[n];
}

// ---------------------------------------------------------------------------
// LayerNorm + adaLN modulate: out = ln(x) * (s+1) + sh
// ---------------------------------------------------------------------------
__global__ __launch_bounds__(256)
void k_lnmod(const float* __restrict__ x, float* __restrict__ out,
             const float* __restrict__ ada, int adaStride, int sOff, int shOff) {
    int r = blockIdx.x;
    int b = r / LSEQ;
    int t = threadIdx.x;
    int lane = t & 31, warp = t >> 5;

    float4 v = ((const float4*)(x + r * DMODEL))[t];
    float sum  = v.x + v.y + v.z + v.w;
    float sums = v.x * v.x + v.y * v.y + v.z * v.z + v.w * v.w;
#pragma unroll
    for (int o = 16; o; o >>= 1) {
        sum  += __shfl_xor_sync(0xffffffffu, sum, o);
        sums += __shfl_xor_sync(0xffffffffu, sums, o);
    }
    __shared__ float rs[8][2];
    if (lane == 0) { rs[warp][0] = sum; rs[warp][1] = sums; }
    __syncthreads();
    float S = 0.f, SS = 0.f;
#pragma unroll
    for (int w = 0; w < 8; w++) { S += rs[w][0]; SS += rs[w][1]; }
    float mean = S * (1.f / DMODEL);
    float var  = SS * (1.f / DMODEL) - mean * mean;
    float rstd = rsqrtf(var + 1e-6f);

    const float* ap = ada + b * adaStride;
    int d = t * 4;
    float4 o;
    o.x = (v.x - mean) * rstd * (ap[sOff + d + 0] + 1.f) + ap[shOff + d + 0];
    o.y = (v.y - mean) * rstd * (ap[sOff + d + 1] + 1.f) + ap[shOff + d + 1];
    o.z = (v.z - mean) * rstd * (ap[sOff + d + 2] + 1.f) + ap[shOff + d + 2];
    o.w = (v.w - mean) * rstd * (ap[sOff + d + 3] + 1.f) + ap[shOff + d + 3];
    ((float4*)(out + r * DMODEL))[t] = o;
}

// ---------------------------------------------------------------------------
// q/k L2 normalization (in place inside g_qkv), q *= exp(q_scale[head])
// grid = ROWS, block = 512 (one warp per head)
// ---------------------------------------------------------------------------
__global__ __launch_bounds__(512)
void k_qknorm(const float* __restrict__ q_scale) {
    int r = blockIdx.x;
    int h = threadIdx.x >> 5;
    int lane = threadIdx.x & 31;
    float* qp = g_qkv + r * (3 * DMODEL) + h * HDIM;
    float* kp = qp + DMODEL;
    float q0 = qp[lane], q1 = qp[lane + 32];
    float k0 = kp[lane], k1 = kp[lane + 32];
    float sq = q0 * q0 + q1 * q1;
    float sk = k0 * k0 + k1 * k1;
#pragma unroll
    for (int o = 16; o; o >>= 1) {
        sq += __shfl_xor_sync(0xffffffffu, sq, o);
        sk += __shfl_xor_sync(0xffffffffu, sk, o);
    }
    float iq = (1.f / fmaxf(sqrtf(sq), 1e-12f)) * expf(q_scale[h]);
    float ik =  1.f / fmaxf(sqrtf(sk), 1e-12f);
    qp[lane] = q0 * iq; qp[lane + 32] = q1 * iq;
    kp[lane] = k0 * ik; kp[lane + 32] = k1 * ik;
}

// ---------------------------------------------------------------------------
// Fused attention: scores + masked softmax + AV, all smem-resident.
// q-tiled by 16. grid (ceil(L/16), H, B), block 128.
// No attention matrix ever touches global memory.
// ---------------------------------------------------------------------------
#define QT 16
__global__ __launch_bounds__(128)
void k_attn_fused() {
    int qt = blockIdx.x * QT;
    int h  = blockIdx.y;
    int b  = blockIdx.z;
    int tid = threadIdx.x;
    int nq = min(QT, LSEQ - qt);

    __shared__ float qs[QT][HDIM];   // q tile; reused as AV partial buffer later
    __shared__ float s[QT][LSEQ];    // scores -> probabilities (in place)

    // ---- load q tile ----
    for (int t = tid; t < QT * HDIM; t += 128) {
        int qi = t >> 6, j = t & 63;
        float val = 0.f;
        if (qi < nq) val = g_qkv[(b * LSEQ + qt + qi) * (3 * DMODEL) + h * HDIM + j];
        qs[qi][j] = val;
    }
    __syncthreads();

    // ---- scores: s[qi][k] = q[qi] . k[k] ----
    int endMax = end_of(qt + nq - 1);
    for (int k = tid; k < endMax; k += 128) {
        const float* kp = g_qkv + (b * LSEQ + k) * (3 * DMODEL) + DMODEL + h * HDIM;
        float acc[QT];
#pragma unroll
        for (int qi = 0; qi < QT; qi++) acc[qi] = 0.f;
#pragma unroll
        for (int j4 = 0; j4 < HDIM; j4 += 4) {
            float4 kv = *(const float4*)(kp + j4);
#pragma unroll
            for (int qi = 0; qi < QT; qi++) {
                acc[qi] += qs[qi][j4 + 0] * kv.x + qs[qi][j4 + 1] * kv.y
                         + qs[qi][j4 + 2] * kv.z + qs[qi][j4 + 3] * kv.w;
            }
        }
#pragma unroll
        for (int qi = 0; qi < QT; qi++) s[qi][k] = acc[qi];
    }
    __syncthreads();

    // ---- softmax in place (one warp per q-row, 4 rows at a time) ----
    // Rows qi >= nq are never read downstream (their output is not stored),
    // but zero them anyway so the AV loop reads defined values.
    int lane = tid & 31, wq = tid >> 5;
    for (int qi0 = 0; qi0 < QT; qi0 += 4) {
        int qi = qi0 + wq;
        if (qi < nq) {
            int q = qt + qi;
            int end = end_of(q);
            float m = -1e30f;
            for (int k = lane; k < end; k += 32) m = fmaxf(m, s[qi][k]);
#pragma unroll
            for (int o = 16; o; o >>= 1) m = fmaxf(m, __shfl_xor_sync(0xffffffffu, m, o));
            float sum = 0.f;
            for (int k = lane; k < end; k += 32) {
                float e = expf(s[qi][k] - m);
                s[qi][k] = e;
                sum += e;
            }
#pragma unroll
            for (int o = 16; o; o >>= 1) sum += __shfl_xor_sync(0xffffffffu, sum, o);
            float inv = 1.f / sum;
            for (int k = lane; k < end; k += 32) s[qi][k] *= inv;
            for (int k = end + lane; k < endMax; k += 32) s[qi][k] = 0.f;
        } else if (qi < QT) {
            for (int k = lane; k < endMax; k += 32) s[qi][k] = 0.f;
        }
    }
    __syncthreads();

    // ---- AV: o[qi][j] = sum_k s[qi][k] * v[k][j] ----
    // Two 64-thread groups split the k range; group 1's partials staged in qs.
    int g = tid >> 6;     // 0 or 1
    int j = tid & 63;
    float acc[QT];
#pragma unroll
    for (int qi = 0; qi < QT; qi++) acc[qi] = 0.f;

    for (int k = g; k < endMax; k += 2) {
        float v = g_qkv[(b * LSEQ + k) * (3 * DMODEL) + 2 * DMODEL + h * HDIM + j];
#pragma unroll
        for (int qi = 0; qi < QT; qi++) acc[qi] += s[qi][k] * v;
    }
    __syncthreads();   // qs no longer needed for q: safe to reuse
    if (g == 1) {
#pragma unroll
        for (int qi = 0; qi < QT; qi++) qs[qi][j] = acc[qi];
    }
    __syncthreads();
    if (g == 0) {
        for (int qi = 0; qi < nq; qi++)
            g_o[(b * LSEQ + qt + qi) * DMODEL + h * HDIM + j] = acc[qi] + qs[qi][j];
    }
}

// ---------------------------------------------------------------------------
// Host launcher
// ---------------------------------------------------------------------------
extern "C" void kernel_launch(void* const* d_in, const int* in_sizes, int n_in,
                              void* d_out, int out_size) {
    (void)in_sizes; (void)n_in; (void)out_size;
    const float* patches    = (const float*)d_in[0];
    const int*   labels     = (const int*)  d_in[1];
    const float* W_patch    = (const float*)d_in[2];
    const float* b_patch    = (const float*)d_in[3];
    const float* pos        = (const float*)d_in[4];
    const float* scale_emb  = (const float*)d_in[5];
    const float* class_emb  = (const float*)d_in[6];
    const float* ada_W      = (const float*)d_in[7];
    const float* ada_b      = (const float*)d_in[8];
    const float* qkv_W      = (const float*)d_in[9];
    const float* qkv_b      = (const float*)d_in[10];
    const float* q_scale    = (const float*)d_in[11];
    const float* proj_W     = (const float*)d_in[12];
    const float* proj_b     = (const float*)d_in[13];
    const float* fc1_W      = (const float*)d_in[14];
    const float* fc1_b      = (const float*)d_in[15];
    const float* fc2_W      = (const float*)d_in[16];
    const float* fc2_b      = (const float*)d_in[17];
    const float* head_ada_W = (const float*)d_in[18];
    const float* head_ada_b = (const float*)d_in[19];
    const float* head_W     = (const float*)d_in[20];
    const float* head_b     = (const float*)d_in[21];
    float* out = (float*)d_out;

    float *x, *h, *qkv, *o, *mlp, *ada, *hada;
    cudaGetSymbolAddress((void**)&x,    g_x);
    cudaGetSymbolAddress((void**)&h,    g_h);
    cudaGetSymbolAddress((void**)&qkv,  g_qkv);
    cudaGetSymbolAddress((void**)&o,    g_o);
    cudaGetSymbolAddress((void**)&mlp,  g_mlp);
    cudaGetSymbolAddress((void**)&ada,  g_ada);
    cudaGetSymbolAddress((void**)&hada, g_hada);

    const int gy = (ROWS + 127) / 128;  // 22

    // cond + patch embed + assemble
    k_cond<<<dim3(4, BATCH), 256>>>(class_emb, labels);
    k_sgemm<<<dim3(DMODEL / 128, (PROWS + 127) / 128), 256>>>(
        patches, W_patch, nullptr, h, PROWS, DMODEL, PDIM, EPI_NONE, 0);
    k_assemble<<<(ROWS * DMODEL + 255) / 256, 256>>>(pos, scale_emb, b_patch);

    for (int i = 0; i < NDEPTH; i++) {
        k_ada<<<(BATCH * 6 * DMODEL + 255) / 256, 256>>>(
            ada_W + i * DMODEL * 6 * DMODEL, ada_b + i * 6 * DMODEL, ada, 6 * DMODEL);
        // h = ln(x)*(s1+1)+sh1   (s1 at 2048, sh1 at 4096)
        k_lnmod<<<ROWS, 256>>>(x, h, ada, 6 * DMODEL, 2 * DMODEL, 4 * DMODEL);
        // qkv
        k_sgemm<<<dim3(3 * DMODEL / 128, gy), 256>>>(
            h, qkv_W + i * DMODEL * 3 * DMODEL, qkv_b + i * 3 * DMODEL,
            qkv, ROWS, 3 * DMODEL, DMODEL, EPI_NONE, 0);
        k_qknorm<<<ROWS, 512>>>(q_scale + i * NHEAD);
        k_attn_fused<<<dim3((LSEQ + QT - 1) / QT, NHEAD, BATCH), 128>>>();
        // x += g1 * (o @ proj_W + proj_b)   (g1 at 0)
        k_sgemm<<<dim3(DMODEL / 128, gy), 256>>>(
            o, proj_W + i * DMODEL * DMODEL, proj_b + i * DMODEL,
            x, ROWS, DMODEL, DMODEL, EPI_GATE, 0);
        // h = ln(x)*(s2+1)+sh2   (s2 at 3072, sh2 at 5120)
        k_lnmod<<<ROWS, 256>>>(x, h, ada, 6 * DMODEL, 3 * DMODEL, 5 * DMODEL);
        // mlp = gelu(h @ fc1 + b1)
        k_sgemm<<<dim3(MLPDIM / 128, gy), 256>>>(
            h, fc1_W + i * DMODEL * MLPDIM, fc1_b + i * MLPDIM,
            mlp, ROWS, MLPDIM, DMODEL, EPI_GELU, 0);
        // x += g2 * (mlp @ fc2 + b2)   (g2 at 1024)
        k_sgemm<<<dim3(DMODEL / 128, gy), 256>>>(
            mlp, fc2_W + i * MLPDIM * DMODEL, fc2_b + i * DMODEL,
            x, ROWS, DMODEL, MLPDIM, EPI_GATE, DMODEL);
    }

    // head
    k_ada<<<(BATCH * 2 * DMODEL + 255) / 256, 256>>>(head_ada_W, head_ada_b, hada, 2 * DMODEL);
    k_lnmod<<<ROWS, 256>>>(x, h, hada, 2 * DMODEL, 0, DMODEL);
    k_sgemm<<<dim3((PDIM + 127) / 128, gy), 256>>>(
        h, head_W, head_b, out, ROWS, PDIM, DMODEL, EPI_NONE, 0);
}

// round 10
// speedup vs baseline: 1.5530x; 1.5530x over previous
#include <cuda_runtime.h>
#include <math.h>
#include <stdint.h>

// ---------------------------------------------------------------------------
// Problem constants
// ---------------------------------------------------------------------------
#define BATCH 8
#define LSEQ 341          // 5 + 16 + 64 + 256
#define PATCH_LEN 340
#define PDIM 192
#define DMODEL 1024
#define NHEAD 16
#define HDIM 64
#define NDEPTH 8
#define MLPDIM 4096
#define ROWS (BATCH * LSEQ)        // 2728
#define PROWS (BATCH * PATCH_LEN)  // 2720

// ---------------------------------------------------------------------------
// Scratch (device globals: no allocation allowed)
// ---------------------------------------------------------------------------
__device__ float g_x[ROWS * DMODEL];
__device__ float g_h[ROWS * DMODEL];
__device__ float g_qkv[ROWS * 3 * DMODEL];
__device__ float g_o[ROWS * DMODEL];
__device__ float g_mlp[ROWS * MLPDIM];
__device__ float g_ada[BATCH * 6 * DMODEL];
__device__ float g_cond[BATCH * DMODEL];
__device__ float g_silu[BATCH * DMODEL];
__device__ float g_hada[BATCH * 2 * DMODEL];

__device__ __forceinline__ int stage_of(int l) {
    return (l < 5) ? 0 : (l < 21) ? 1 : (l < 85) ? 2 : 3;
}
__device__ __forceinline__ int end_of(int l) {
    return (l < 5) ? 5 : (l < 21) ? 21 : (l < 85) ? 85 : 341;
}

__device__ __forceinline__ float gelu_tanh(float x) {
    float x3 = x * x * x;
    return 0.5f * x * (1.f + tanhf(0.7978845608028654f * (x + 0.044715f * x3)));
}

__device__ __forceinline__ uint32_t f2tf32(float x) {
    uint32_t r;
    asm("cvt.rna.tf32.f32 %0, %1;" : "=r"(r) : "f"(x));
    return r;
}

// ---------------------------------------------------------------------------
// cond gather + silu
// ---------------------------------------------------------------------------
__global__ void k_cond(const float* __restrict__ class_emb,
                       const int* __restrict__ labels) {
    int b = blockIdx.y;
    int d = blockIdx.x * 256 + threadIdx.x;
    float c = class_emb[labels[b] * DMODEL + d];
    g_cond[b * DMODEL + d] = c;
    g_silu[b * DMODEL + d] = c / (1.f + expf(-c));
}

// ---------------------------------------------------------------------------
// Assemble x = concat(cond, tok) + pos + scale_emb[SID] (+ b_patch on tok)
// ---------------------------------------------------------------------------
__global__ void k_assemble(const float* __restrict__ pos,
                           const float* __restrict__ scale_emb,
                           const float* __restrict__ b_patch) {
    int idx = blockIdx.x * 256 + threadIdx.x;
    if (idx >= ROWS * DMODEL) return;
    int d = idx & (DMODEL - 1);
    int r = idx >> 10;
    int b = r / LSEQ;
    int l = r - b * LSEQ;
    float v;
    if (l == 0) v = g_cond[b * DMODEL + d];
    else        v = g_h[(b * PATCH_LEN + l - 1) * DMODEL + d] + b_patch[d];
    v += pos[l * DMODEL + d] + scale_emb[stage_of(l) * DMODEL + d];
    g_x[idx] = v;
}

// ---------------------------------------------------------------------------
// TF32 tensor-core GEMM (mma.sync.m16n8k8), double-buffered.
// C[M,N] = A[M,K] @ B[K,N] (+ bias) + epilogue.  K % 16 == 0.
// Block 256 thr = 8 warps (4 M x 2 N), block tile 128x128, warp tile 32x64.
// smem rows padded to 136 floats: fragment-load banks (m + 8k) mod 32 are
// fully distinct -> conflict-free LDS.
// epi: 0=none, 1=gelu, 2=gated residual (C += gate * (acc+bias)), gate from
//      g_ada[b*6144 + gateOff + col], b = row / LSEQ.
// ---------------------------------------------------------------------------
#define EPI_NONE 0
#define EPI_GELU 1
#define EPI_GATE 2
#define SPAD 136

__global__ __launch_bounds__(256)
void k_sgemm(const float* __restrict__ A, const float* __restrict__ Bm,
             const float* __restrict__ bias, float* __restrict__ C,
             int M, int N, int K, int epi, int gateOff) {
    __shared__ float As[2][16][SPAD];
    __shared__ float Bs[2][16][SPAD];

    int tid = threadIdx.x;
    int brow = blockIdx.y * 128;
    int bcol = blockIdx.x * 128;

    int ar  = tid >> 2;           // 0..63   (A row within tile, +64 for s=1)
    int ac4 = (tid & 3) * 4;      // 0,4,8,12 (A k-offset, float4)
    int br  = tid >> 5;           // 0..7    (B k-row within tile, +8 for s=1)
    int bc4 = (tid & 31) * 4;     // 0..124  (B col, float4)

    int wid  = tid >> 5;
    int lane = tid & 31;
    int gid  = lane >> 2;         // groupID 0..7
    int tgrp = lane & 3;          // threadID_in_group 0..3
    int mbase = (wid >> 1) * 32;  // warp M offset within tile
    int nbase = (wid & 1) * 64;   // warp N offset within tile

    // c[mf][nf][0..3]
    float c[2][8][4];
#pragma unroll
    for (int mf = 0; mf < 2; mf++)
#pragma unroll
        for (int nf = 0; nf < 8; nf++)
#pragma unroll
            for (int e = 0; e < 4; e++) c[mf][nf][e] = 0.f;

    const int nk = K >> 4;
    float4 aReg[2], bReg[2];

    // ---- prologue: load tile 0 into buffer 0 ----
#pragma unroll
    for (int s = 0; s < 2; s++) {
        int row = brow + ar + s * 64;
        aReg[s] = make_float4(0.f, 0.f, 0.f, 0.f);
        if (row < M) aReg[s] = *(const float4*)(A + row * K + ac4);
        int kr = br + s * 8;
        int col = bcol + bc4;
        bReg[s] = make_float4(0.f, 0.f, 0.f, 0.f);
        if (col < N) bReg[s] = *(const float4*)(Bm + kr * N + col);
    }
#pragma unroll
    for (int s = 0; s < 2; s++) {
        As[0][ac4 + 0][ar + s * 64] = __uint_as_float(f2tf32(aReg[s].x));
        As[0][ac4 + 1][ar + s * 64] = __uint_as_float(f2tf32(aReg[s].y));
        As[0][ac4 + 2][ar + s * 64] = __uint_as_float(f2tf32(aReg[s].z));
        As[0][ac4 + 3][ar + s * 64] = __uint_as_float(f2tf32(aReg[s].w));
        Bs[0][br + s * 8][bc4 + 0] = __uint_as_float(f2tf32(bReg[s].x));
        Bs[0][br + s * 8][bc4 + 1] = __uint_as_float(f2tf32(bReg[s].y));
        Bs[0][br + s * 8][bc4 + 2] = __uint_as_float(f2tf32(bReg[s].z));
        Bs[0][br + s * 8][bc4 + 3] = __uint_as_float(f2tf32(bReg[s].w));
    }
    __syncthreads();

    for (int kt = 0; kt < nk; kt++) {
        int p = kt & 1;

        // ---- issue global loads for next tile (overlap with compute) ----
        if (kt + 1 < nk) {
            int k0n = (kt + 1) << 4;
#pragma unroll
            for (int s = 0; s < 2; s++) {
                int row = brow + ar + s * 64;
                aReg[s] = make_float4(0.f, 0.f, 0.f, 0.f);
                if (row < M) aReg[s] = *(const float4*)(A + row * K + k0n + ac4);
                int kr = k0n + br + s * 8;
                int col = bcol + bc4;
                bReg[s] = make_float4(0.f, 0.f, 0.f, 0.f);
                if (col < N) bReg[s] = *(const float4*)(Bm + kr * N + col);
            }
        }

        // ---- compute on buffer p: two k8 steps ----
#pragma unroll
        for (int ks = 0; ks < 16; ks += 8) {
            uint32_t af[2][4];
#pragma unroll
            for (int mf = 0; mf < 2; mf++) {
                int m = mbase + mf * 16 + gid;
                af[mf][0] = __float_as_uint(As[p][ks + tgrp][m]);
                af[mf][1] = __float_as_uint(As[p][ks + tgrp][m + 8]);
                af[mf][2] = __float_as_uint(As[p][ks + tgrp + 4][m]);
                af[mf][3] = __float_as_uint(As[p][ks + tgrp + 4][m + 8]);
            }
            uint32_t bf[8][2];
#pragma unroll
            for (int nf = 0; nf < 8; nf++) {
                int n = nbase + nf * 8 + gid;
                bf[nf][0] = __float_as_uint(Bs[p][ks + tgrp][n]);
                bf[nf][1] = __float_as_uint(Bs[p][ks + tgrp + 4][n]);
            }
#pragma unroll
            for (int mf = 0; mf < 2; mf++)
#pragma unroll
                for (int nf = 0; nf < 8; nf++) {
                    asm volatile(
                        "mma.sync.aligned.m16n8k8.row.col.f32.tf32.tf32.f32 "
                        "{%0,%1,%2,%3}, {%4,%5,%6,%7}, {%8,%9}, {%0,%1,%2,%3};\n"
                        : "+f"(c[mf][nf][0]), "+f"(c[mf][nf][1]),
                          "+f"(c[mf][nf][2]), "+f"(c[mf][nf][3])
                        : "r"(af[mf][0]), "r"(af[mf][1]), "r"(af[mf][2]), "r"(af[mf][3]),
                          "r"(bf[nf][0]), "r"(bf[nf][1]));
                }
        }

        // ---- stage next tile into the other buffer ----
        if (kt + 1 < nk) {
            int q = p ^ 1;
#pragma unroll
            for (int s = 0; s < 2; s++) {
                As[q][ac4 + 0][ar + s * 64] = __uint_as_float(f2tf32(aReg[s].x));
                As[q][ac4 + 1][ar + s * 64] = __uint_as_float(f2tf32(aReg[s].y));
                As[q][ac4 + 2][ar + s * 64] = __uint_as_float(f2tf32(aReg[s].z));
                As[q][ac4 + 3][ar + s * 64] = __uint_as_float(f2tf32(aReg[s].w));
                Bs[q][br + s * 8][bc4 + 0] = __uint_as_float(f2tf32(bReg[s].x));
                Bs[q][br + s * 8][bc4 + 1] = __uint_as_float(f2tf32(bReg[s].y));
                Bs[q][br + s * 8][bc4 + 2] = __uint_as_float(f2tf32(bReg[s].z));
                Bs[q][br + s * 8][bc4 + 3] = __uint_as_float(f2tf32(bReg[s].w));
            }
            __syncthreads();
        }
    }

    // ---- epilogue ----
#pragma unroll
    for (int mf = 0; mf < 2; mf++) {
        int r0 = brow + mbase + mf * 16 + gid;
#pragma unroll
        for (int nf = 0; nf < 8; nf++) {
            int c0 = bcol + nbase + nf * 8 + tgrp * 2;
            float b0 = (bias && c0 < N)     ? bias[c0]     : 0.f;
            float b1 = (bias && c0 + 1 < N) ? bias[c0 + 1] : 0.f;
#pragma unroll
            for (int half = 0; half < 2; half++) {
                int row = r0 + half * 8;
                if (row >= M) continue;
                int bidx = row / LSEQ;
#pragma unroll
                for (int e = 0; e < 2; e++) {
                    int col = c0 + e;
                    if (col >= N) continue;
                    float v = c[mf][nf][half * 2 + e] + (e ? b1 : b0);
                    int off = row * N + col;
                    if (epi == EPI_GELU) {
                        C[off] = gelu_tanh(v);
                    } else if (epi == EPI_GATE) {
                        float g = g_ada[bidx * 6144 + gateOff + col];
                        C[off] = C[off] + g * v;
                    } else {
                        C[off] = v;
                    }
                }
            }
        }
    }
}

// ---------------------------------------------------------------------------
// ada = silu(cond) @ W + b: one thread per output column, all 8 batches.
// W read exactly once. silu preloaded to smem (broadcast reads).
// ---------------------------------------------------------------------------
__global__ __launch_bounds__(256)
void k_ada(const float* __restrict__ W, const float* __restrict__ bias,
           float* __restrict__ out, int N) {
    __shared__ float s[BATCH][DMODEL];   // 32 KB
    int tid = threadIdx.x;
    for (int i = tid; i < BATCH * DMODEL; i += 256)
        s[i >> 10][i & (DMODEL - 1)] = g_silu[i];
    __syncthreads();

    int n = blockIdx.x * 256 + tid;
    if (n >= N) return;

    float acc[BATCH];
#pragma unroll
    for (int b = 0; b < BATCH; b++) acc[b] = 0.f;

    for (int k = 0; k < DMODEL; k += 4) {
        float w0 = W[(k + 0) * N + n];
        float w1 = W[(k + 1) * N + n];
        float w2 = W[(k + 2) * N + n];
        float w3 = W[(k + 3) * N + n];
#pragma unroll
        for (int b = 0; b < BATCH; b++)
            acc[b] += s[b][k] * w0 + s[b][k + 1] * w1
                    + s[b][k + 2] * w2 + s[b][k + 3] * w3;
    }
    float bb = bias[n];
#pragma unroll
    for (int b = 0; b < BATCH; b++) out[b * N + n] = acc[b] + bb;
}

// ---------------------------------------------------------------------------
// LayerNorm + adaLN modulate: out = ln(x) * (s+1) + sh
// ---------------------------------------------------------------------------
__global__ __launch_bounds__(256)
void k_lnmod(const float* __restrict__ x, float* __restrict__ out,
             const float* __restrict__ ada, int adaStride, int sOff, int shOff) {
    int r = blockIdx.x;
    int b = r / LSEQ;
    int t = threadIdx.x;
    int lane = t & 31, warp = t >> 5;

    float4 v = ((const float4*)(x + r * DMODEL))[t];
    float sum  = v.x + v.y + v.z + v.w;
    float sums = v.x * v.x + v.y * v.y + v.z * v.z + v.w * v.w;
#pragma unroll
    for (int o = 16; o; o >>= 1) {
        sum  += __shfl_xor_sync(0xffffffffu, sum, o);
        sums += __shfl_xor_sync(0xffffffffu, sums, o);
    }
    __shared__ float rs[8][2];
    if (lane == 0) { rs[warp][0] = sum; rs[warp][1] = sums; }
    __syncthreads();
    float S = 0.f, SS = 0.f;
#pragma unroll
    for (int w = 0; w < 8; w++) { S += rs[w][0]; SS += rs[w][1]; }
    float mean = S * (1.f / DMODEL);
    float var  = SS * (1.f / DMODEL) - mean * mean;
    float rstd = rsqrtf(var + 1e-6f);

    const float* ap = ada + b * adaStride;
    int d = t * 4;
    float4 o;
    o.x = (v.x - mean) * rstd * (ap[sOff + d + 0] + 1.f) + ap[shOff + d + 0];
    o.y = (v.y - mean) * rstd * (ap[sOff + d + 1] + 1.f) + ap[shOff + d + 1];
    o.z = (v.z - mean) * rstd * (ap[sOff + d + 2] + 1.f) + ap[shOff + d + 2];
    o.w = (v.w - mean) * rstd * (ap[sOff + d + 3] + 1.f) + ap[shOff + d + 3];
    ((float4*)(out + r * DMODEL))[t] = o;
}

// ---------------------------------------------------------------------------
// q/k L2 normalization (in place inside g_qkv), q *= exp(q_scale[head])
// grid = ROWS, block = 512 (one warp per head)
// ---------------------------------------------------------------------------
__global__ __launch_bounds__(512)
void k_qknorm(const float* __restrict__ q_scale) {
    int r = blockIdx.x;
    int h = threadIdx.x >> 5;
    int lane = threadIdx.x & 31;
    float* qp = g_qkv + r * (3 * DMODEL) + h * HDIM;
    float* kp = qp + DMODEL;
    float q0 = qp[lane], q1 = qp[lane + 32];
    float k0 = kp[lane], k1 = kp[lane + 32];
    float sq = q0 * q0 + q1 * q1;
    float sk = k0 * k0 + k1 * k1;
#pragma unroll
    for (int o = 16; o; o >>= 1) {
        sq += __shfl_xor_sync(0xffffffffu, sq, o);
        sk += __shfl_xor_sync(0xffffffffu, sk, o);
    }
    float iq = (1.f / fmaxf(sqrtf(sq), 1e-12f)) * expf(q_scale[h]);
    float ik =  1.f / fmaxf(sqrtf(sk), 1e-12f);
    qp[lane] = q0 * iq; qp[lane + 32] = q1 * iq;
    kp[lane] = k0 * ik; kp[lane + 32] = k1 * ik;
}

// ---------------------------------------------------------------------------
// Fused attention: scores + masked softmax + AV, all smem-resident.
// q-tiled by 16. grid (ceil(L/16), H, B), block 128.
// ---------------------------------------------------------------------------
#define QT 16
__global__ __launch_bounds__(128)
void k_attn_fused() {
    int qt = blockIdx.x * QT;
    int h  = blockIdx.y;
    int b  = blockIdx.z;
    int tid = threadIdx.x;
    int nq = min(QT, LSEQ - qt);

    __shared__ float qs[QT][HDIM];   // q tile; reused as AV partial buffer later
    __shared__ float s[QT][LSEQ];    // scores -> probabilities (in place)

    // ---- load q tile ----
    for (int t = tid; t < QT * HDIM; t += 128) {
        int qi = t >> 6, j = t & 63;
        float val = 0.f;
        if (qi < nq) val = g_qkv[(b * LSEQ + qt + qi) * (3 * DMODEL) + h * HDIM + j];
        qs[qi][j] = val;
    }
    __syncthreads();

    // ---- scores ----
    int endMax = end_of(qt + nq - 1);
    for (int k = tid; k < endMax; k += 128) {
        const float* kp = g_qkv + (b * LSEQ + k) * (3 * DMODEL) + DMODEL + h * HDIM;
        float acc[QT];
#pragma unroll
        for (int qi = 0; qi < QT; qi++) acc[qi] = 0.f;
#pragma unroll
        for (int j4 = 0; j4 < HDIM; j4 += 4) {
            float4 kv = *(const float4*)(kp + j4);
#pragma unroll
            for (int qi = 0; qi < QT; qi++) {
                acc[qi] += qs[qi][j4 + 0] * kv.x + qs[qi][j4 + 1] * kv.y
                         + qs[qi][j4 + 2] * kv.z + qs[qi][j4 + 3] * kv.w;
            }
        }
#pragma unroll
        for (int qi = 0; qi < QT; qi++) s[qi][k] = acc[qi];
    }
    __syncthreads();

    // ---- softmax in place ----
    int lane = tid & 31, wq = tid >> 5;
    for (int qi0 = 0; qi0 < QT; qi0 += 4) {
        int qi = qi0 + wq;
        if (qi < nq) {
            int q = qt + qi;
            int end = end_of(q);
            float m = -1e30f;
            for (int k = lane; k < end; k += 32) m = fmaxf(m, s[qi][k]);
#pragma unroll
            for (int o = 16; o; o >>= 1) m = fmaxf(m, __shfl_xor_sync(0xffffffffu, m, o));
            float sum = 0.f;
            for (int k = lane; k < end; k += 32) {
                float e = expf(s[qi][k] - m);
                s[qi][k] = e;
                sum += e;
            }
#pragma unroll
            for (int o = 16; o; o >>= 1) sum += __shfl_xor_sync(0xffffffffu, sum, o);
            float inv = 1.f / sum;
            for (int k = lane; k < end; k += 32) s[qi][k] *= inv;
            for (int k = end + lane; k < endMax; k += 32) s[qi][k] = 0.f;
        } else if (qi < QT) {
            for (int k = lane; k < endMax; k += 32) s[qi][k] = 0.f;
        }
    }
    __syncthreads();

    // ---- AV ----
    int g = tid >> 6;     // 0 or 1
    int j = tid & 63;
    float acc[QT];
#pragma unroll
    for (int qi = 0; qi < QT; qi++) acc[qi] = 0.f;

    for (int k = g; k < endMax; k += 2) {
        float v = g_qkv[(b * LSEQ + k) * (3 * DMODEL) + 2 * DMODEL + h * HDIM + j];
#pragma unroll
        for (int qi = 0; qi < QT; qi++) acc[qi] += s[qi][k] * v;
    }
    __syncthreads();
    if (g == 1) {
#pragma unroll
        for (int qi = 0; qi < QT; qi++) qs[qi][j] = acc[qi];
    }
    __syncthreads();
    if (g == 0) {
        for (int qi = 0; qi < nq; qi++)
            g_o[(b * LSEQ + qt + qi) * DMODEL + h * HDIM + j] = acc[qi] + qs[qi][j];
    }
}

// ---------------------------------------------------------------------------
// Host launcher
// ---------------------------------------------------------------------------
extern "C" void kernel_launch(void* const* d_in, const int* in_sizes, int n_in,
                              void* d_out, int out_size) {
    (void)in_sizes; (void)n_in; (void)out_size;
    const float* patches    = (const float*)d_in[0];
    const int*   labels     = (const int*)  d_in[1];
    const float* W_patch    = (const float*)d_in[2];
    const float* b_patch    = (const float*)d_in[3];
    const float* pos        = (const float*)d_in[4];
    const float* scale_emb  = (const float*)d_in[5];
    const float* class_emb  = (const float*)d_in[6];
    const float* ada_W      = (const float*)d_in[7];
    const float* ada_b      = (const float*)d_in[8];
    const float* qkv_W      = (const float*)d_in[9];
    const float* qkv_b      = (const float*)d_in[10];
    const float* q_scale    = (const float*)d_in[11];
    const float* proj_W     = (const float*)d_in[12];
    const float* proj_b     = (const float*)d_in[13];
    const float* fc1_W      = (const float*)d_in[14];
    const float* fc1_b      = (const float*)d_in[15];
    const float* fc2_W      = (const float*)d_in[16];
    const float* fc2_b      = (const float*)d_in[17];
    const float* head_ada_W = (const float*)d_in[18];
    const float* head_ada_b = (const float*)d_in[19];
    const float* head_W     = (const float*)d_in[20];
    const float* head_b     = (const float*)d_in[21];
    float* out = (float*)d_out;

    float *x, *h, *qkv, *o, *mlp, *ada, *hada;
    cudaGetSymbolAddress((void**)&x,    g_x);
    cudaGetSymbolAddress((void**)&h,    g_h);
    cudaGetSymbolAddress((void**)&qkv,  g_qkv);
    cudaGetSymbolAddress((void**)&o,    g_o);
    cudaGetSymbolAddress((void**)&mlp,  g_mlp);
    cudaGetSymbolAddress((void**)&ada,  g_ada);
    cudaGetSymbolAddress((void**)&hada, g_hada);

    const int gy = (ROWS + 127) / 128;  // 22

    // cond + patch embed + assemble
    k_cond<<<dim3(4, BATCH), 256>>>(class_emb, labels);
    k_sgemm<<<dim3(DMODEL / 128, (PROWS + 127) / 128), 256>>>(
        patches, W_patch, nullptr, h, PROWS, DMODEL, PDIM, EPI_NONE, 0);
    k_assemble<<<(ROWS * DMODEL + 255) / 256, 256>>>(pos, scale_emb, b_patch);

    for (int i = 0; i < NDEPTH; i++) {
        k_ada<<<(6 * DMODEL + 255) / 256, 256>>>(
            ada_W + i * DMODEL * 6 * DMODEL, ada_b + i * 6 * DMODEL, ada, 6 * DMODEL);
        // h = ln(x)*(s1+1)+sh1   (s1 at 2048, sh1 at 4096)
        k_lnmod<<<ROWS, 256>>>(x, h, ada, 6 * DMODEL, 2 * DMODEL, 4 * DMODEL);
        // qkv
        k_sgemm<<<dim3(3 * DMODEL / 128, gy), 256>>>(
            h, qkv_W + i * DMODEL * 3 * DMODEL, qkv_b + i * 3 * DMODEL,
            qkv, ROWS, 3 * DMODEL, DMODEL, EPI_NONE, 0);
        k_qknorm<<<ROWS, 512>>>(q_scale + i * NHEAD);
        k_attn_fused<<<dim3((LSEQ + QT - 1) / QT, NHEAD, BATCH), 128>>>();
        // x += g1 * (o @ proj_W + proj_b)   (g1 at 0)
        k_sgemm<<<dim3(DMODEL / 128, gy), 256>>>(
            o, proj_W + i * DMODEL * DMODEL, proj_b + i * DMODEL,
            x, ROWS, DMODEL, DMODEL, EPI_GATE, 0);
        // h = ln(x)*(s2+1)+sh2   (s2 at 3072, sh2 at 5120)
        k_lnmod<<<ROWS, 256>>>(x, h, ada, 6 * DMODEL, 3 * DMODEL, 5 * DMODEL);
        // mlp = gelu(h @ fc1 + b1)
        k_sgemm<<<dim3(MLPDIM / 128, gy), 256>>>(
            h, fc1_W + i * DMODEL * MLPDIM, fc1_b + i * MLPDIM,
            mlp, ROWS, MLPDIM, DMODEL, EPI_GELU, 0);
        // x += g2 * (mlp @ fc2 + b2)   (g2 at 1024)
        k_sgemm<<<dim3(DMODEL / 128, gy), 256>>>(
            mlp, fc2_W + i * MLPDIM * DMODEL, fc2_b + i * DMODEL,
            x, ROWS, DMODEL, MLPDIM, EPI_GATE, DMODEL);
    }

    // head
    k_ada<<<(2 * DMODEL + 255) / 256, 256>>>(head_ada_W, head_ada_b, hada, 2 * DMODEL);
    k_lnmod<<<ROWS, 256>>>(x, h, hada, 2 * DMODEL, 0, DMODEL);
    k_sgemm<<<dim3((PDIM + 127) / 128, gy), 256>>>(
        h, head_W, head_b, out, ROWS, PDIM, DMODEL, EPI_NONE, 0);
}

// round 12
// speedup vs baseline: 1.6919x; 1.0895x over previous
#include <cuda_runtime.h>
#include <math.h>
#include <stdint.h>

// ---------------------------------------------------------------------------
// Problem constants
// ---------------------------------------------------------------------------
#define BATCH 8
#define LSEQ 341          // 5 + 16 + 64 + 256
#define PATCH_LEN 340
#define PDIM 192
#define DMODEL 1024
#define NHEAD 16
#define HDIM 64
#define NDEPTH 8
#define MLPDIM 4096
#define ROWS (BATCH * LSEQ)        // 2728
#define PROWS (BATCH * PATCH_LEN)  // 2720
#define KSLICE 8                   // k_ada split-K slices

// ---------------------------------------------------------------------------
// Scratch (device globals: no allocation allowed)
// ---------------------------------------------------------------------------
__device__ float g_x[ROWS * DMODEL];
__device__ float g_h[ROWS * DMODEL];
__device__ float g_qkv[ROWS * 3 * DMODEL];
__device__ float g_o[ROWS * DMODEL];
__device__ float g_mlp[ROWS * MLPDIM];
__device__ float g_ada[BATCH * 6 * DMODEL];
__device__ float g_adap[KSLICE * BATCH * 6 * DMODEL];   // ada partials
__device__ float g_cond[BATCH * DMODEL];
__device__ float g_silu[BATCH * DMODEL];
__device__ float g_hada[BATCH * 2 * DMODEL];

__device__ __forceinline__ int stage_of(int l) {
    return (l < 5) ? 0 : (l < 21) ? 1 : (l < 85) ? 2 : 3;
}
__device__ __forceinline__ int end_of(int l) {
    return (l < 5) ? 5 : (l < 21) ? 21 : (l < 85) ? 85 : 341;
}

__device__ __forceinline__ float gelu_tanh(float x) {
    float x3 = x * x * x;
    return 0.5f * x * (1.f + tanhf(0.7978845608028654f * (x + 0.044715f * x3)));
}

__device__ __forceinline__ uint32_t f2tf32(float x) {
    uint32_t r;
    asm("cvt.rna.tf32.f32 %0, %1;" : "=r"(r) : "f"(x));
    return r;
}

// ---------------------------------------------------------------------------
// cond gather + silu
// ---------------------------------------------------------------------------
__global__ void k_cond(const float* __restrict__ class_emb,
                       const int* __restrict__ labels) {
    int b = blockIdx.y;
    int d = blockIdx.x * 256 + threadIdx.x;
    float c = class_emb[labels[b] * DMODEL + d];
    g_cond[b * DMODEL + d] = c;
    g_silu[b * DMODEL + d] = c / (1.f + expf(-c));
}

// ---------------------------------------------------------------------------
// Assemble x = concat(cond, tok) + pos + scale_emb[SID] (+ b_patch on tok)
// ---------------------------------------------------------------------------
__global__ void k_assemble(const float* __restrict__ pos,
                           const float* __restrict__ scale_emb,
                           const float* __restrict__ b_patch) {
    int idx = blockIdx.x * 256 + threadIdx.x;
    if (idx >= ROWS * DMODEL) return;
    int d = idx & (DMODEL - 1);
    int r = idx >> 10;
    int b = r / LSEQ;
    int l = r - b * LSEQ;
    float v;
    if (l == 0) v = g_cond[b * DMODEL + d];
    else        v = g_h[(b * PATCH_LEN + l - 1) * DMODEL + d] + b_patch[d];
    v += pos[l * DMODEL + d] + scale_emb[stage_of(l) * DMODEL + d];
    g_x[idx] = v;
}

// ---------------------------------------------------------------------------
// TF32 tensor-core GEMM (mma.sync.m16n8k8), double-buffered, templated on
// the N-tile width NT (128 or 64).
// C[M,N] = A[M,K] @ B[K,N] (+ bias) + epilogue.  K % 16 == 0.
// Block 256 thr = 8 warps (4 M x 2 N); warp tile 32 x (NT/2).
// As rows padded to 136 floats, Bs rows padded to (NT==128?136:72):
// both ≡ 8 mod 32 -> fragment-load banks (k*8 + n) mod 32 all distinct.
// epi: 0=none, 1=gelu, 2=gated residual (C += gate * (acc+bias)), gate from
//      g_ada[b*6144 + gateOff + col], b = row / LSEQ.
// ---------------------------------------------------------------------------
#define EPI_NONE 0
#define EPI_GELU 1
#define EPI_GATE 2
#define SPAD 136

template <int NT>
__global__ __launch_bounds__(256)
void k_sgemm(const float* __restrict__ A, const float* __restrict__ Bm,
             const float* __restrict__ bias, float* __restrict__ C,
             int M, int N, int K, int epi, int gateOff) {
    constexpr int SPB = (NT == 128) ? 136 : 72;
    constexpr int NF  = NT / 16;            // 8 or 4
    constexpr int BPASS = (NT == 128) ? 2 : 1;

    __shared__ float As[2][16][SPAD];
    __shared__ float Bs[2][16][SPB];

    int tid = threadIdx.x;
    int brow = blockIdx.y * 128;
    int bcol = blockIdx.x * NT;

    int ar  = tid >> 2;                       // 0..63
    int ac4 = (tid & 3) * 4;                  // 0,4,8,12
    int brB = (NT == 128) ? (tid >> 5) : (tid >> 4);   // 0..7 / 0..15
    int bc4 = (NT == 128) ? (tid & 31) * 4 : (tid & 15) * 4;

    int wid  = tid >> 5;
    int lane = tid & 31;
    int gid  = lane >> 2;
    int tgrp = lane & 3;
    int mbase = (wid >> 1) * 32;
    int nbase = (wid & 1) * (NT / 2);

    float c[2][NF][4];
#pragma unroll
    for (int mf = 0; mf < 2; mf++)
#pragma unroll
        for (int nf = 0; nf < NF; nf++)
#pragma unroll
            for (int e = 0; e < 4; e++) c[mf][nf][e] = 0.f;

    const int nk = K >> 4;
    float4 aReg[2], bReg[BPASS];

    // ---- prologue: load tile 0 into buffer 0 ----
#pragma unroll
    for (int s = 0; s < 2; s++) {
        int row = brow + ar + s * 64;
        aReg[s] = make_float4(0.f, 0.f, 0.f, 0.f);
        if (row < M) aReg[s] = *(const float4*)(A + row * K + ac4);
    }
#pragma unroll
    for (int s = 0; s < BPASS; s++) {
        int kr = brB + s * 8;
        int col = bcol + bc4;
        bReg[s] = make_float4(0.f, 0.f, 0.f, 0.f);
        if (col < N) bReg[s] = *(const float4*)(Bm + kr * N + col);
    }
#pragma unroll
    for (int s = 0; s < 2; s++) {
        As[0][ac4 + 0][ar + s * 64] = __uint_as_float(f2tf32(aReg[s].x));
        As[0][ac4 + 1][ar + s * 64] = __uint_as_float(f2tf32(aReg[s].y));
        As[0][ac4 + 2][ar + s * 64] = __uint_as_float(f2tf32(aReg[s].z));
        As[0][ac4 + 3][ar + s * 64] = __uint_as_float(f2tf32(aReg[s].w));
    }
#pragma unroll
    for (int s = 0; s < BPASS; s++) {
        Bs[0][brB + s * 8][bc4 + 0] = __uint_as_float(f2tf32(bReg[s].x));
        Bs[0][brB + s * 8][bc4 + 1] = __uint_as_float(f2tf32(bReg[s].y));
        Bs[0][brB + s * 8][bc4 + 2] = __uint_as_float(f2tf32(bReg[s].z));
        Bs[0][brB + s * 8][bc4 + 3] = __uint_as_float(f2tf32(bReg[s].w));
    }
    __syncthreads();

    for (int kt = 0; kt < nk; kt++) {
        int p = kt & 1;

        // ---- issue global loads for next tile (overlap with compute) ----
        if (kt + 1 < nk) {
            int k0n = (kt + 1) << 4;
#pragma unroll
            for (int s = 0; s < 2; s++) {
                int row = brow + ar + s * 64;
                aReg[s] = make_float4(0.f, 0.f, 0.f, 0.f);
                if (row < M) aReg[s] = *(const float4*)(A + row * K + k0n + ac4);
            }
#pragma unroll
            for (int s = 0; s < BPASS; s++) {
                int kr = k0n + brB + s * 8;
                int col = bcol + bc4;
                bReg[s] = make_float4(0.f, 0.f, 0.f, 0.f);
                if (col < N) bReg[s] = *(const float4*)(Bm + kr * N + col);
            }
        }

        // ---- compute on buffer p: two k8 steps ----
#pragma unroll
        for (int ks = 0; ks < 16; ks += 8) {
            uint32_t af[2][4];
#pragma unroll
            for (int mf = 0; mf < 2; mf++) {
                int m = mbase + mf * 16 + gid;
                af[mf][0] = __float_as_uint(As[p][ks + tgrp][m]);
                af[mf][1] = __float_as_uint(As[p][ks + tgrp][m + 8]);
                af[mf][2] = __float_as_uint(As[p][ks + tgrp + 4][m]);
                af[mf][3] = __float_as_uint(As[p][ks + tgrp + 4][m + 8]);
            }
            uint32_t bf[NF][2];
#pragma unroll
            for (int nf = 0; nf < NF; nf++) {
                int n = nbase + nf * 8 + gid;
                bf[nf][0] = __float_as_uint(Bs[p][ks + tgrp][n]);
                bf[nf][1] = __float_as_uint(Bs[p][ks + tgrp + 4][n]);
            }
#pragma unroll
            for (int mf = 0; mf < 2; mf++)
#pragma unroll
                for (int nf = 0; nf < NF; nf++) {
                    asm volatile(
                        "mma.sync.aligned.m16n8k8.row.col.f32.tf32.tf32.f32 "
                        "{%0,%1,%2,%3}, {%4,%5,%6,%7}, {%8,%9}, {%0,%1,%2,%3};\n"
                        : "+f"(c[mf][nf][0]), "+f"(c[mf][nf][1]),
                          "+f"(c[mf][nf][2]), "+f"(c[mf][nf][3])
                        : "r"(af[mf][0]), "r"(af[mf][1]), "r"(af[mf][2]), "r"(af[mf][3]),
                          "r"(bf[nf][0]), "r"(bf[nf][1]));
                }
        }

        // ---- stage next tile into the other buffer ----
        if (kt + 1 < nk) {
            int q = p ^ 1;
#pragma unroll
            for (int s = 0; s < 2; s++) {
                As[q][ac4 + 0][ar + s * 64] = __uint_as_float(f2tf32(aReg[s].x));
                As[q][ac4 + 1][ar + s * 64] = __uint_as_float(f2tf32(aReg[s].y));
                As[q][ac4 + 2][ar + s * 64] = __uint_as_float(f2tf32(aReg[s].z));
                As[q][ac4 + 3][ar + s * 64] = __uint_as_float(f2tf32(aReg[s].w));
            }
#pragma unroll
            for (int s = 0; s < BPASS; s++) {
                Bs[q][brB + s * 8][bc4 + 0] = __uint_as_float(f2tf32(bReg[s].x));
                Bs[q][brB + s * 8][bc4 + 1] = __uint_as_float(f2tf32(bReg[s].y));
                Bs[q][brB + s * 8][bc4 + 2] = __uint_as_float(f2tf32(bReg[s].z));
                Bs[q][brB + s * 8][bc4 + 3] = __uint_as_float(f2tf32(bReg[s].w));
            }
            __syncthreads();
        }
    }

    // ---- epilogue ----
#pragma unroll
    for (int mf = 0; mf < 2; mf++) {
        int r0 = brow + mbase + mf * 16 + gid;
#pragma unroll
        for (int nf = 0; nf < NF; nf++) {
            int c0 = bcol + nbase + nf * 8 + tgrp * 2;
            float b0 = (bias && c0 < N)     ? bias[c0]     : 0.f;
            float b1 = (bias && c0 + 1 < N) ? bias[c0 + 1] : 0.f;
#pragma unroll
            for (int half = 0; half < 2; half++) {
                int row = r0 + half * 8;
                if (row >= M) continue;
                int bidx = row / LSEQ;
#pragma unroll
                for (int e = 0; e < 2; e++) {
                    int col = c0 + e;
                    if (col >= N) continue;
                    float v = c[mf][nf][half * 2 + e] + (e ? b1 : b0);
                    int off = row * N + col;
                    if (epi == EPI_GELU) {
                        C[off] = gelu_tanh(v);
                    } else if (epi == EPI_GATE) {
                        float g = g_ada[bidx * 6144 + gateOff + col];
                        C[off] = C[off] + g * v;
                    } else {
                        C[off] = v;
                    }
                }
            }
        }
    }
}

// ---------------------------------------------------------------------------
// ada = silu(cond) @ W + b, split-K two-phase.
// Phase 1: grid (N/256, KSLICE). Each block handles a 128-wide k-slice for
// 256 columns, all 8 batches; W read exactly once chip-wide.
// Phase 2: deterministic reduce of KSLICE partials + bias.
// ---------------------------------------------------------------------------
__global__ __launch_bounds__(256)
void k_ada_part(const float* __restrict__ W, int N) {
    int ks = blockIdx.y;
    __shared__ float s[BATCH][128];   // 4 KB silu slice
    int tid = threadIdx.x;
    for (int i = tid; i < BATCH * 128; i += 256) {
        int b = i >> 7, kk = i & 127;
        s[b][kk] = g_silu[b * DMODEL + ks * 128 + kk];
    }
    __syncthreads();

    int n = blockIdx.x * 256 + tid;
    if (n >= N) return;

    float acc[BATCH];
#pragma unroll
    for (int b = 0; b < BATCH; b++) acc[b] = 0.f;

    const float* Wp = W + (size_t)(ks * 128) * N + n;
    for (int k = 0; k < 128; k += 4) {
        float w0 = Wp[(size_t)(k + 0) * N];
        float w1 = Wp[(size_t)(k + 1) * N];
        float w2 = Wp[(size_t)(k + 2) * N];
        float w3 = Wp[(size_t)(k + 3) * N];
#pragma unroll
        for (int b = 0; b < BATCH; b++)
            acc[b] += s[b][k] * w0 + s[b][k + 1] * w1
                    + s[b][k + 2] * w2 + s[b][k + 3] * w3;
    }
#pragma unroll
    for (int b = 0; b < BATCH; b++)
        g_adap[((size_t)ks * BATCH + b) * N + n] = acc[b];
}

__global__ __launch_bounds__(256)
void k_ada_red(const float* __restrict__ bias, float* __restrict__ out, int N) {
    int t = blockIdx.x * 256 + threadIdx.x;
    if (t >= BATCH * N) return;
    int b = t / N;
    int n = t - b * N;
    float a = bias[n];
#pragma unroll
    for (int ks = 0; ks < KSLICE; ks++)
        a += g_adap[((size_t)ks * BATCH + b) * N + n];
    out[t] = a;
}

// ---------------------------------------------------------------------------
// LayerNorm + adaLN modulate: out = ln(x) * (s+1) + sh
// ---------------------------------------------------------------------------
__global__ __launch_bounds__(256)
void k_lnmod(const float* __restrict__ x, float* __restrict__ out,
             const float* __restrict__ ada, int adaStride, int sOff, int shOff) {
    int r = blockIdx.x;
    int b = r / LSEQ;
    int t = threadIdx.x;
    int lane = t & 31, warp = t >> 5;

    float4 v = ((const float4*)(x + r * DMODEL))[t];
    float sum  = v.x + v.y + v.z + v.w;
    float sums = v.x * v.x + v.y * v.y + v.z * v.z + v.w * v.w;
#pragma unroll
    for (int o = 16; o; o >>= 1) {
        sum  += __shfl_xor_sync(0xffffffffu, sum, o);
        sums += __shfl_xor_sync(0xffffffffu, sums, o);
    }
    __shared__ float rs[8][2];
    if (lane == 0) { rs[warp][0] = sum; rs[warp][1] = sums; }
    __syncthreads();
    float S = 0.f, SS = 0.f;
#pragma unroll
    for (int w = 0; w < 8; w++) { S += rs[w][0]; SS += rs[w][1]; }
    float mean = S * (1.f / DMODEL);
    float var  = SS * (1.f / DMODEL) - mean * mean;
    float rstd = rsqrtf(var + 1e-6f);

    const float* ap = ada + b * adaStride;
    int d = t * 4;
    float4 o;
    o.x = (v.x - mean) * rstd * (ap[sOff + d + 0] + 1.f) + ap[shOff + d + 0];
    o.y = (v.y - mean) * rstd * (ap[sOff + d + 1] + 1.f) + ap[shOff + d + 1];
    o.z = (v.z - mean) * rstd * (ap[sOff + d + 2] + 1.f) + ap[shOff + d + 2];
    o.w = (v.w - mean) * rstd * (ap[sOff + d + 3] + 1.f) + ap[shOff + d + 3];
    ((float4*)(out + r * DMODEL))[t] = o;
}

// ---------------------------------------------------------------------------
// q/k L2 normalization (in place inside g_qkv), q *= exp(q_scale[head])
// grid = ROWS, block = 512 (one warp per head)
// ---------------------------------------------------------------------------
__global__ __launch_bounds__(512)
void k_qknorm(const float* __restrict__ q_scale) {
    int r = blockIdx.x;
    int h = threadIdx.x >> 5;
    int lane = threadIdx.x & 31;
    float* qp = g_qkv + r * (3 * DMODEL) + h * HDIM;
    float* kp = qp + DMODEL;
    float q0 = qp[lane], q1 = qp[lane + 32];
    float k0 = kp[lane], k1 = kp[lane + 32];
    float sq = q0 * q0 + q1 * q1;
    float sk = k0 * k0 + k1 * k1;
#pragma unroll
    for (int o = 16; o; o >>= 1) {
        sq += __shfl_xor_sync(0xffffffffu, sq, o);
        sk += __shfl_xor_sync(0xffffffffu, sk, o);
    }
    float iq = (1.f / fmaxf(sqrtf(sq), 1e-12f)) * expf(q_scale[h]);
    float ik =  1.f / fmaxf(sqrtf(sk), 1e-12f);
    qp[lane] = q0 * iq; qp[lane + 32] = q1 * iq;
    kp[lane] = k0 * ik; kp[lane + 32] = k1 * ik;
}

// ---------------------------------------------------------------------------
// Fused attention: scores + masked softmax + AV, all smem-resident.
// q-tiled by 16. grid (ceil(L/16), H, B), block 128.
// ---------------------------------------------------------------------------
#define QT 16
__global__ __launch_bounds__(128)
void k_attn_fused() {
    int qt = blockIdx.x * QT;
    int h  = blockIdx.y;
    int b  = blockIdx.z;
    int tid = threadIdx.x;
    int nq = min(QT, LSEQ - qt);

    __shared__ float qs[QT][HDIM];   // q tile; reused as AV partial buffer later
    __shared__ float s[QT][LSEQ];    // scores -> probabilities (in place)

    // ---- load q tile ----
    for (int t = tid; t < QT * HDIM; t += 128) {
        int qi = t >> 6, j = t & 63;
        float val = 0.f;
        if (qi < nq) val = g_qkv[(b * LSEQ + qt + qi) * (3 * DMODEL) + h * HDIM + j];
        qs[qi][j] = val;
    }
    __syncthreads();

    // ---- scores ----
    int endMax = end_of(qt + nq - 1);
    for (int k = tid; k < endMax; k += 128) {
        const float* kp = g_qkv + (b * LSEQ + k) * (3 * DMODEL) + DMODEL + h * HDIM;
        float acc[QT];
#pragma unroll
        for (int qi = 0; qi < QT; qi++) acc[qi] = 0.f;
#pragma unroll
        for (int j4 = 0; j4 < HDIM; j4 += 4) {
            float4 kv = *(const float4*)(kp + j4);
#pragma unroll
            for (int qi = 0; qi < QT; qi++) {
                acc[qi] += qs[qi][j4 + 0] * kv.x + qs[qi][j4 + 1] * kv.y
                         + qs[qi][j4 + 2] * kv.z + qs[qi][j4 + 3] * kv.w;
            }
        }
#pragma unroll
        for (int qi = 0; qi < QT; qi++) s[qi][k] = acc[qi];
    }
    __syncthreads();

    // ---- softmax in place ----
    int lane = tid & 31, wq = tid >> 5;
    for (int qi0 = 0; qi0 < QT; qi0 += 4) {
        int qi = qi0 + wq;
        if (qi < nq) {
            int q = qt + qi;
            int end = end_of(q);
            float m = -1e30f;
            for (int k = lane; k < end; k += 32) m = fmaxf(m, s[qi][k]);
#pragma unroll
            for (int o = 16; o; o >>= 1) m = fmaxf(m, __shfl_xor_sync(0xffffffffu, m, o));
            float sum = 0.f;
            for (int k = lane; k < end; k += 32) {
                float e = expf(s[qi][k] - m);
                s[qi][k] = e;
                sum += e;
            }
#pragma unroll
            for (int o = 16; o; o >>= 1) sum += __shfl_xor_sync(0xffffffffu, sum, o);
            float inv = 1.f / sum;
            for (int k = lane; k < end; k += 32) s[qi][k] *= inv;
            for (int k = end + lane; k < endMax; k += 32) s[qi][k] = 0.f;
        } else if (qi < QT) {
            for (int k = lane; k < endMax; k += 32) s[qi][k] = 0.f;
        }
    }
    __syncthreads();

    // ---- AV ----
    int g = tid >> 6;     // 0 or 1
    int j = tid & 63;
    float acc[QT];
#pragma unroll
    for (int qi = 0; qi < QT; qi++) acc[qi] = 0.f;

    for (int k = g; k < endMax; k += 2) {
        float v = g_qkv[(b * LSEQ + k) * (3 * DMODEL) + 2 * DMODEL + h * HDIM + j];
#pragma unroll
        for (int qi = 0; qi < QT; qi++) acc[qi] += s[qi][k] * v;
    }
    __syncthreads();
    if (g == 1) {
#pragma unroll
        for (int qi = 0; qi < QT; qi++) qs[qi][j] = acc[qi];
    }
    __syncthreads();
    if (g == 0) {
        for (int qi = 0; qi < nq; qi++)
            g_o[(b * LSEQ + qt + qi) * DMODEL + h * HDIM + j] = acc[qi] + qs[qi][j];
    }
}

// ---------------------------------------------------------------------------
// Host launcher
// ---------------------------------------------------------------------------
extern "C" void kernel_launch(void* const* d_in, const int* in_sizes, int n_in,
                              void* d_out, int out_size) {
    (void)in_sizes; (void)n_in; (void)out_size;
    const float* patches    = (const float*)d_in[0];
    const int*   labels     = (const int*)  d_in[1];
    const float* W_patch    = (const float*)d_in[2];
    const float* b_patch    = (const float*)d_in[3];
    const float* pos        = (const float*)d_in[4];
    const float* scale_emb  = (const float*)d_in[5];
    const float* class_emb  = (const float*)d_in[6];
    const float* ada_W      = (const float*)d_in[7];
    const float* ada_b      = (const float*)d_in[8];
    const float* qkv_W      = (const float*)d_in[9];
    const float* qkv_b      = (const float*)d_in[10];
    const float* q_scale    = (const float*)d_in[11];
    const float* proj_W     = (const float*)d_in[12];
    const float* proj_b     = (const float*)d_in[13];
    const float* fc1_W      = (const float*)d_in[14];
    const float* fc1_b      = (const float*)d_in[15];
    const float* fc2_W      = (const float*)d_in[16];
    const float* fc2_b      = (const float*)d_in[17];
    const float* head_ada_W = (const float*)d_in[18];
    const float* head_ada_b = (const float*)d_in[19];
    const float* head_W     = (const float*)d_in[20];
    const float* head_b     = (const float*)d_in[21];
    float* out = (float*)d_out;

    float *x, *h, *qkv, *o, *mlp, *ada, *hada;
    cudaGetSymbolAddress((void**)&x,    g_x);
    cudaGetSymbolAddress((void**)&h,    g_h);
    cudaGetSymbolAddress((void**)&qkv,  g_qkv);
    cudaGetSymbolAddress((void**)&o,    g_o);
    cudaGetSymbolAddress((void**)&mlp,  g_mlp);
    cudaGetSymbolAddress((void**)&ada,  g_ada);
    cudaGetSymbolAddress((void**)&hada, g_hada);

    const int gy = (ROWS + 127) / 128;  // 22

    // cond + patch embed + assemble
    k_cond<<<dim3(4, BATCH), 256>>>(class_emb, labels);
    k_sgemm<64><<<dim3(DMODEL / 64, (PROWS + 127) / 128), 256>>>(
        patches, W_patch, nullptr, h, PROWS, DMODEL, PDIM, EPI_NONE, 0);
    k_assemble<<<(ROWS * DMODEL + 255) / 256, 256>>>(pos, scale_emb, b_patch);

    for (int i = 0; i < NDEPTH; i++) {
        // ada = silu(cond) @ ada_W + ada_b  (split-K two-phase)
        k_ada_part<<<dim3(6 * DMODEL / 256, KSLICE), 256>>>(
            ada_W + (size_t)i * DMODEL * 6 * DMODEL, 6 * DMODEL);
        k_ada_red<<<(BATCH * 6 * DMODEL + 255) / 256, 256>>>(
            ada_b + i * 6 * DMODEL, ada, 6 * DMODEL);
        // h = ln(x)*(s1+1)+sh1   (s1 at 2048, sh1 at 4096)
        k_lnmod<<<ROWS, 256>>>(x, h, ada, 6 * DMODEL, 2 * DMODEL, 4 * DMODEL);
        // qkv
        k_sgemm<128><<<dim3(3 * DMODEL / 128, gy), 256>>>(
            h, qkv_W + (size_t)i * DMODEL * 3 * DMODEL, qkv_b + i * 3 * DMODEL,
            qkv, ROWS, 3 * DMODEL, DMODEL, EPI_NONE, 0);
        k_qknorm<<<ROWS, 512>>>(q_scale + i * NHEAD);
        k_attn_fused<<<dim3((LSEQ + QT - 1) / QT, NHEAD, BATCH), 128>>>();
        // x += g1 * (o @ proj_W + proj_b)   (g1 at 0)
        k_sgemm<64><<<dim3(DMODEL / 64, gy), 256>>>(
            o, proj_W + (size_t)i * DMODEL * DMODEL, proj_b + i * DMODEL,
            x, ROWS, DMODEL, DMODEL, EPI_GATE, 0);
        // h = ln(x)*(s2+1)+sh2   (s2 at 3072, sh2 at 5120)
        k_lnmod<<<ROWS, 256>>>(x, h, ada, 6 * DMODEL, 3 * DMODEL, 5 * DMODEL);
        // mlp = gelu(h @ fc1 + b1)
        k_sgemm<128><<<dim3(MLPDIM / 128, gy), 256>>>(
            h, fc1_W + (size_t)i * DMODEL * MLPDIM, fc1_b + i * MLPDIM,
            mlp, ROWS, MLPDIM, DMODEL, EPI_GELU, 0);
        // x += g2 * (mlp @ fc2 + b2)   (g2 at 1024)
        k_sgemm<64><<<dim3(DMODEL / 64, gy), 256>>>(
            mlp, fc2_W + (size_t)i * MLPDIM * DMODEL, fc2_b + i * DMODEL,
            x, ROWS, DMODEL, MLPDIM, EPI_GATE, DMODEL);
    }

    // head
    k_ada_part<<<dim3(2 * DMODEL / 256, KSLICE), 256>>>(head_ada_W, 2 * DMODEL);
    k_ada_red<<<(BATCH * 2 * DMODEL + 255) / 256, 256>>>(head_ada_b, hada, 2 * DMODEL);
    k_lnmod<<<ROWS, 256>>>(x, h, hada, 2 * DMODEL, 0, DMODEL);
    k_sgemm<64><<<dim3((PDIM + 63) / 64, gy), 256>>>(
        h, head_W, head_b, out, ROWS, PDIM, DMODEL, EPI_NONE, 0);
}